// round 8
// baseline (speedup 1.0000x reference)
#include <cuda_runtime.h>

// relu(x @ W^T + b)
// x: [B*N, 2] f32, W: [256, 2] f32 row-major (W[d][i]), b: [256] f32
// out: [B*N, 256] f32.  n_rows = 512000.
//
// R6 resubmit (infra failure): warp-per-row, each thread -> 8 CONTIGUOUS
// columns (lane*8), emitted as ONE 256-bit streaming store
// (st.global.cs.v8.f32, sm_100a). One warp store instruction = one full
// 1024B row. Weights/bias loaded as float4 vectors.

#define BLOCK_THREADS 256
#define ROWS_PER_BLOCK 8               // 8 warps = 8 concurrent rows
#define ITERS 16                       // -> 128 rows per block

__device__ __forceinline__ void stg256_cs(float* p,
                                          float a0, float a1, float a2, float a3,
                                          float a4, float a5, float a6, float a7) {
    asm volatile("st.global.cs.v8.f32 [%0], {%1,%2,%3,%4,%5,%6,%7,%8};"
                 :: "l"(p), "f"(a0), "f"(a1), "f"(a2), "f"(a3),
                            "f"(a4), "f"(a5), "f"(a6), "f"(a7)
                 : "memory");
}

__global__ __launch_bounds__(BLOCK_THREADS)
void embeddings_kernel(const float* __restrict__ x,
                       const float* __restrict__ W,
                       const float* __restrict__ b,
                       float* __restrict__ out,
                       int n_rows) {
    int tid  = threadIdx.x;
    int lane = tid & 31;               // 0..31 -> 8-col chunk (cols lane*8..lane*8+7)
    int sub  = tid >> 5;               // warp id -> row subgroup

    // W pairs for cols [lane*8, lane*8+8): 16 contiguous floats = 4 float4.
    const float4* __restrict__ W4 = reinterpret_cast<const float4*>(W);
    float4 w0 = __ldg(&W4[lane * 4 + 0]);   // {Wx,Wy} for cols c+0, c+1
    float4 w1 = __ldg(&W4[lane * 4 + 1]);   // cols c+2, c+3
    float4 w2 = __ldg(&W4[lane * 4 + 2]);   // cols c+4, c+5
    float4 w3 = __ldg(&W4[lane * 4 + 3]);   // cols c+6, c+7
    const float4* __restrict__ b4 = reinterpret_cast<const float4*>(b);
    float4 bv0 = __ldg(&b4[lane * 2 + 0]);  // bias c+0..c+3
    float4 bv1 = __ldg(&b4[lane * 2 + 1]);  // bias c+4..c+7

    int row0 = blockIdx.x * (ROWS_PER_BLOCK * ITERS) + sub;

    const float2* __restrict__ xp = reinterpret_cast<const float2*>(x) + row0;
    float* __restrict__ op = out + (size_t)row0 * 256 + lane * 8;

    int rows_left = n_rows - row0;

    #pragma unroll 4
    for (int i = 0; i < ITERS; i++) {
        if (i * ROWS_PER_BLOCK >= rows_left) break;

        float2 xx = __ldg(xp);         // one broadcast load per warp per row

        float y0 = fmaxf(fmaf(xx.x, w0.x, fmaf(xx.y, w0.y, bv0.x)), 0.0f);
        float y1 = fmaxf(fmaf(xx.x, w0.z, fmaf(xx.y, w0.w, bv0.y)), 0.0f);
        float y2 = fmaxf(fmaf(xx.x, w1.x, fmaf(xx.y, w1.y, bv0.z)), 0.0f);
        float y3 = fmaxf(fmaf(xx.x, w1.z, fmaf(xx.y, w1.w, bv0.w)), 0.0f);
        float y4 = fmaxf(fmaf(xx.x, w2.x, fmaf(xx.y, w2.y, bv1.x)), 0.0f);
        float y5 = fmaxf(fmaf(xx.x, w2.z, fmaf(xx.y, w2.w, bv1.y)), 0.0f);
        float y6 = fmaxf(fmaf(xx.x, w3.x, fmaf(xx.y, w3.y, bv1.z)), 0.0f);
        float y7 = fmaxf(fmaf(xx.x, w3.z, fmaf(xx.y, w3.w, bv1.w)), 0.0f);

        stg256_cs(op, y0, y1, y2, y3, y4, y5, y6, y7);

        xp += ROWS_PER_BLOCK;
        op += ROWS_PER_BLOCK * 256;
    }
}

extern "C" void kernel_launch(void* const* d_in, const int* in_sizes, int n_in,
                              void* d_out, int out_size) {
    const float* x = (const float*)d_in[0];   // [B, N, 2]
    const float* W = (const float*)d_in[1];   // [256, 2]
    const float* b = (const float*)d_in[2];   // [256]
    float* out = (float*)d_out;               // [B, N, 256]

    int n_rows = in_sizes[0] / 2;             // B*N = 512000

    int rows_per_block = ROWS_PER_BLOCK * ITERS;   // 128
    int grid = (n_rows + rows_per_block - 1) / rows_per_block;   // 4000
    embeddings_kernel<<<grid, BLOCK_THREADS>>>(x, W, b, out, n_rows);
}

// round 9
// speedup vs baseline: 1.1498x; 1.1498x over previous
#include <cuda_runtime.h>

// relu(x @ W^T + b)
// x: [B*N, 2] f32, W: [256, 2] f32 row-major (W[d][i]), b: [256] f32
// out: [B*N, 256] f32.  n_rows = 512000.
//
// R9: revert to R5 structure (best: two STG.128.CS per thread, warp-per-row)
// + vectorized float4 weight/bias prologue + 512-thread blocks.
// Chunk A = cols [lane*4, lane*4+4), chunk B = A + 128.

#define BLOCK_THREADS 512
#define ROWS_PER_BLOCK 16              // 16 warps = 16 concurrent rows
#define ITERS 16                       // -> 256 rows per block

__global__ __launch_bounds__(BLOCK_THREADS)
void embeddings_kernel(const float* __restrict__ x,
                       const float* __restrict__ W,
                       const float* __restrict__ b,
                       float* __restrict__ out,
                       int n_rows) {
    int tid  = threadIdx.x;
    int lane = tid & 31;               // 0..31
    int sub  = tid >> 5;               // warp id -> row subgroup

    // Chunk A: cols [lane*4, lane*4+4)  -> W floats [lane*8, lane*8+8) = 2 float4
    // Chunk B: cols A+128               -> W floats offset +256 = +64 float4
    const float4* __restrict__ W4 = reinterpret_cast<const float4*>(W);
    float4 wa0 = __ldg(&W4[lane * 2 + 0]);      // {Wx,Wy} cols A+0, A+1
    float4 wa1 = __ldg(&W4[lane * 2 + 1]);      // cols A+2, A+3
    float4 wb0 = __ldg(&W4[lane * 2 + 64]);     // cols B+0, B+1
    float4 wb1 = __ldg(&W4[lane * 2 + 65]);     // cols B+2, B+3
    const float4* __restrict__ b4 = reinterpret_cast<const float4*>(b);
    float4 ba = __ldg(&b4[lane]);               // bias cols A+0..A+3
    float4 bb = __ldg(&b4[lane + 32]);          // bias cols B+0..B+3

    int row0 = blockIdx.x * (ROWS_PER_BLOCK * ITERS) + sub;

    const float2* __restrict__ xp = reinterpret_cast<const float2*>(x) + row0;
    float4* __restrict__ opA = reinterpret_cast<float4*>(out) + row0 * 64 + lane;
    float4* __restrict__ opB = opA + 32;        // +128 floats

    int rows_left = n_rows - row0;

    #pragma unroll 4
    for (int i = 0; i < ITERS; i++) {
        if (i * ROWS_PER_BLOCK >= rows_left) break;

        float2 xx = __ldg(xp);         // one broadcast load per warp per row

        float4 ya, yb;
        ya.x = fmaxf(fmaf(xx.x, wa0.x, fmaf(xx.y, wa0.y, ba.x)), 0.0f);
        ya.y = fmaxf(fmaf(xx.x, wa0.z, fmaf(xx.y, wa0.w, ba.y)), 0.0f);
        ya.z = fmaxf(fmaf(xx.x, wa1.x, fmaf(xx.y, wa1.y, ba.z)), 0.0f);
        ya.w = fmaxf(fmaf(xx.x, wa1.z, fmaf(xx.y, wa1.w, ba.w)), 0.0f);
        yb.x = fmaxf(fmaf(xx.x, wb0.x, fmaf(xx.y, wb0.y, bb.x)), 0.0f);
        yb.y = fmaxf(fmaf(xx.x, wb0.z, fmaf(xx.y, wb0.w, bb.y)), 0.0f);
        yb.z = fmaxf(fmaf(xx.x, wb1.x, fmaf(xx.y, wb1.y, bb.z)), 0.0f);
        yb.w = fmaxf(fmaf(xx.x, wb1.z, fmaf(xx.y, wb1.w, bb.w)), 0.0f);

        __stcs(opA, ya);               // two independent coalesced streaming stores
        __stcs(opB, yb);

        xp  += ROWS_PER_BLOCK;
        opA += ROWS_PER_BLOCK * 64;
        opB += ROWS_PER_BLOCK * 64;
    }
}

extern "C" void kernel_launch(void* const* d_in, const int* in_sizes, int n_in,
                              void* d_out, int out_size) {
    const float* x = (const float*)d_in[0];   // [B, N, 2]
    const float* W = (const float*)d_in[1];   // [256, 2]
    const float* b = (const float*)d_in[2];   // [256]
    float* out = (float*)d_out;               // [B, N, 256]

    int n_rows = in_sizes[0] / 2;             // B*N = 512000

    int rows_per_block = ROWS_PER_BLOCK * ITERS;   // 256
    int grid = (n_rows + rows_per_block - 1) / rows_per_block;   // 2000
    embeddings_kernel<<<grid, BLOCK_THREADS>>>(x, W, b, out, n_rows);
}